// round 6
// baseline (speedup 1.0000x reference)
#include <cuda_runtime.h>
#include <cuda_bf16.h>
#include <cuda_fp16.h>
#include <math.h>

// Problem constants
#define PP   256
#define FF   20
#define HH   18
#define WW   18
#define HW   (HH*WW)      // 324
#define VOL  (FF*HH*WW)   // 6480
#define MAXB 4096
#define PI_F 3.14159f

// Sampler quad volume: per layer 20x20 quads (8B each), 20 layers + 1 zero layer
#define PJ    20
#define PL2   (PJ*PJ)        // 400
#define ZLAY  (FF*PL2)       // 8000 = zero layer offset
#define PTOT  (ZLAY + PL2)   // 8400 quads = 67200 B

// Per-(b,f) params: c, s, scale, tx, ty  (stride 5)
__device__ float g_params[MAXB * FF * 5];

// ---------------------------------------------------------------------------
// f32x2 helpers
// ---------------------------------------------------------------------------
typedef unsigned long long u64;

__device__ __forceinline__ u64 pack2dup(float v) {
    u64 d;
    asm("mov.b64 %0, {%1, %1};" : "=l"(d) : "r"(__float_as_uint(v)));
    return d;
}
__device__ __forceinline__ u64 fma2(u64 a, u64 b, u64 c) {
    u64 d;
    asm("fma.rn.f32x2 %0, %1, %2, %3;" : "=l"(d) : "l"(a), "l"(b), "l"(c));
    return d;
}
__device__ __forceinline__ float2 unpack2(u64 v) {
    unsigned lo, hi;
    asm("mov.b64 {%0, %1}, %2;" : "=r"(lo), "=r"(hi) : "l"(v));
    float2 f; f.x = __uint_as_float(lo); f.y = __uint_as_float(hi);
    return f;
}

// ---------------------------------------------------------------------------
// Fused params kernel: phase 1 h = relu(pc@W1+b1) (BM=16, BN=256, BK=16),
// phase 2 heads (B x 80) from SMEM h + staged head weights, then activations.
// 256 threads, grid = ceil(B/16).
// ---------------------------------------------------------------------------
#define BM   16
#define BK   16
#define AS_S 18          // As stride (floats)
#define BS_S 260         // Bs stride (floats)
#define HS_S 18          // hs stride (floats)
#define WS_S 84          // head-weight tile stride (floats)

// smem: phase1 As[16][18]=288 | Bs[16][260]=4160  (total 4448)
//       phase2 hs[256][18]=4608 | Ws_s[32][84]=2688 (total 7296)
#define SM_FLOATS 7296

__device__ __forceinline__ float4 head_bias(int cg,
    const float* bs, const float* br, const float* bt)
{
    if (cg < 5)  return ((const float4*)bs)[cg];
    if (cg < 10) return ((const float4*)br)[cg - 5];
    return ((const float4*)bt)[cg - 10];
}

__device__ __forceinline__ void head_store(int row, int B, int cg, const float* o4)
{
    if (row >= B) return;
    float* pb = g_params + (size_t)row * (FF * 5);
    if (cg < 5) {
        #pragma unroll
        for (int ci = 0; ci < 4; ci++)
            pb[(cg * 4 + ci) * 5 + 2] = 2.f / (1.f + expf(-o4[ci]));
    } else if (cg < 10) {
        #pragma unroll
        for (int ci = 0; ci < 4; ci++) {
            float ang = tanhf(o4[ci]) * PI_F;
            int f = (cg - 5) * 4 + ci;
            pb[f * 5 + 0] = cosf(ang);
            pb[f * 5 + 1] = sinf(ang);
        }
    } else {
        #pragma unroll
        for (int ci = 0; ci < 4; ci++) {
            int o = (cg - 10) * 4 + ci;
            pb[(o >> 1) * 5 + 3 + (o & 1)] = tanhf(o4[ci]);
        }
    }
}

__global__ __launch_bounds__(256) void adaat_params_kernel(
    const float* __restrict__ pc, int B,
    const float* __restrict__ W1, const float* __restrict__ b1,
    const float* __restrict__ Ws, const float* __restrict__ bs,
    const float* __restrict__ Wr, const float* __restrict__ br,
    const float* __restrict__ Wt, const float* __restrict__ bt)
{
    __shared__ float sm[SM_FLOATS];
    float* As   = sm;              // [kk][row]   phase 1
    float* Bs   = sm + 288;        // [kk][col]   phase 1
    float* hs   = sm;              // [hid][row]  phase 2 (overlaps As/Bs)
    float* Ws_s = sm + 4608;       // [kk][80]    phase 2

    const int b0  = blockIdx.x * BM;
    const int tid = threadIdx.x;

    // ---------------- phase 1: 16 x 256 GEMM ----------------
    const int tc = tid & 31;       // col group: cols tc*8 .. +7
    const int tr = tid >> 5;       // row pair:  rows tr*2, tr*2+1

    u64 acc[2][4];
    {
        ulonglong2 bl = *(const ulonglong2*)(b1 + tc * 8);
        ulonglong2 bh = *(const ulonglong2*)(b1 + tc * 8 + 4);
        acc[0][0] = bl.x; acc[0][1] = bl.y; acc[0][2] = bh.x; acc[0][3] = bh.y;
        acc[1][0] = bl.x; acc[1][1] = bl.y; acc[1][2] = bh.x; acc[1][3] = bh.y;
    }

    for (int kt = 0; kt < PP; kt += BK) {
        // A tile: pc[b0+row][kt+kk] -> As[kk][row]
        {
            int row = tid >> 4;            // 0..15
            int kk  = tid & 15;
            float v = (b0 + row < B) ? pc[(size_t)(b0 + row) * PP + kt + kk] : 0.f;
            As[kk * AS_S + row] = v;
        }
        // B tile: W1[kt+kk][col] -> Bs[kk][col], float4 coalesced
        #pragma unroll
        for (int p = 0; p < 4; p++) {
            int i  = p * 256 + tid;
            int kk = i >> 6;
            int c4 = i & 63;
            *(float4*)(Bs + kk * BS_S + c4 * 4) =
                *(const float4*)(W1 + (size_t)(kt + kk) * PP + c4 * 4);
        }
        __syncthreads();

        #pragma unroll
        for (int kk = 0; kk < BK; kk++) {
            float2 a = *(const float2*)(As + kk * AS_S + tr * 2);
            ulonglong2 w01 = *(const ulonglong2*)(Bs + kk * BS_S + tc * 8);
            ulonglong2 w23 = *(const ulonglong2*)(Bs + kk * BS_S + tc * 8 + 4);
            u64 a0 = pack2dup(a.x), a1 = pack2dup(a.y);
            acc[0][0] = fma2(a0, w01.x, acc[0][0]);
            acc[0][1] = fma2(a0, w01.y, acc[0][1]);
            acc[0][2] = fma2(a0, w23.x, acc[0][2]);
            acc[0][3] = fma2(a0, w23.y, acc[0][3]);
            acc[1][0] = fma2(a1, w01.x, acc[1][0]);
            acc[1][1] = fma2(a1, w01.y, acc[1][1]);
            acc[1][2] = fma2(a1, w23.x, acc[1][2]);
            acc[1][3] = fma2(a1, w23.y, acc[1][3]);
        }
        __syncthreads();
    }

    // relu -> hs[col][row]
    #pragma unroll
    for (int r = 0; r < 2; r++) {
        #pragma unroll
        for (int j = 0; j < 4; j++) {
            float2 v = unpack2(acc[r][j]);
            int col = tc * 8 + 2 * j;
            int row = tr * 2 + r;
            hs[(col + 0) * HS_S + row] = fmaxf(v.x, 0.f);
            hs[(col + 1) * HS_S + row] = fmaxf(v.y, 0.f);
        }
    }
    __syncthreads();

    // ---------------- phase 2: heads (16 x 80) ----------------
    // tasks: t in [0,320): r = t/20, cg = t%20.  Thread owns t=tid and t=256+tid (tid<64).
    const int  ra  = tid / 20,        cga = tid - ra * 20;
    const int  tb  = 256 + tid;
    const int  rb  = tb / 20,         cgb = tb - rb * 20;
    const bool hasB = (tid < 64);

    float oa[4], ob[4];
    {
        float4 ba = head_bias(cga, bs, br, bt);
        oa[0] = ba.x; oa[1] = ba.y; oa[2] = ba.z; oa[3] = ba.w;
        float4 bb2 = head_bias(hasB ? cgb : 0, bs, br, bt);
        ob[0] = bb2.x; ob[1] = bb2.y; ob[2] = bb2.z; ob[3] = bb2.w;
    }

    for (int kt = 0; kt < PP; kt += 32) {
        // stage [Ws|Wr|Wt] rows kt..kt+31 -> Ws_s[kk][0..79]
        for (int idx = tid; idx < 32 * 80; idx += 256) {
            int kk = idx / 80;
            int c  = idx - kk * 80;
            int k  = kt + kk;
            float v;
            if (c < 20)      v = Ws[(size_t)k * 20 + c];
            else if (c < 40) v = Wr[(size_t)k * 20 + (c - 20)];
            else             v = Wt[(size_t)k * 40 + (c - 40)];
            Ws_s[kk * WS_S + c] = v;
        }
        __syncthreads();

        #pragma unroll 4
        for (int kk = 0; kk < 32; kk++) {
            float  ha = hs[(kt + kk) * HS_S + ra];
            float4 wa = *(const float4*)(Ws_s + kk * WS_S + cga * 4);
            oa[0] = fmaf(ha, wa.x, oa[0]);
            oa[1] = fmaf(ha, wa.y, oa[1]);
            oa[2] = fmaf(ha, wa.z, oa[2]);
            oa[3] = fmaf(ha, wa.w, oa[3]);
            if (hasB) {
                float  hb = hs[(kt + kk) * HS_S + rb];
                float4 wb = *(const float4*)(Ws_s + kk * WS_S + cgb * 4);
                ob[0] = fmaf(hb, wb.x, ob[0]);
                ob[1] = fmaf(hb, wb.y, ob[1]);
                ob[2] = fmaf(hb, wb.z, ob[2]);
                ob[3] = fmaf(hb, wb.w, ob[3]);
            }
        }
        __syncthreads();
    }

    head_store(b0 + ra, B, cga, oa);
    if (hasB) head_store(b0 + rb, B, cgb, ob);
}

// ---------------------------------------------------------------------------
// Sampler: one CTA per batch element, block (18,18).
// SMEM holds 8-byte quads: quad[z][py][pj] =
//   { V(pj-1,py-1), V(pj,py-1) | V(pj-1,py), V(pj,py) }  (two half2)
// so a full bilinear tap set per z-layer is ONE LDS.64. Layer 20 is all-zero
// (used for the z-border blend).
// ---------------------------------------------------------------------------
__global__ __launch_bounds__(324) void adaat_sample_kernel(
    const float* __restrict__ fm, float* __restrict__ out)
{
    extern __shared__ uint2 quads[];   // PTOT entries = 67200 B

    const int b   = blockIdx.x;
    const int tx  = threadIdx.x;       // 0..17
    const int ty  = threadIdx.y;       // 0..17
    const int tid = ty * WW + tx;

    __shared__ float4 cfA[FF];         // axx, axy, cx, wz
    __shared__ float4 cfB[FF];         // ayx, ayy, cy, bits(zb0 | zb1<<16)

    // zero all quads (8400 uint2 = 4200 uint4)
    {
        uint4* q4 = (uint4*)quads;
        for (int i = tid; i < PTOT / 2; i += HW)
            q4[i] = make_uint4(0u, 0u, 0u, 0u);
    }
    __syncthreads();

    // fill quads
    {
        const float* src = fm + (size_t)b * VOL + ty * WW + tx;
        const bool xr = (tx < WW - 1), yd = (ty < HH - 1);
        #pragma unroll 4
        for (int z = 0; z < FF; z++) {
            float v00 = src[z * HW];
            float v10 = xr ? src[z * HW + 1] : 0.f;
            float v01 = yd ? src[z * HW + WW] : 0.f;
            float v11 = (xr && yd) ? src[z * HW + WW + 1] : 0.f;
            __half2 lo = __floats2half2_rn(v00, v10);
            __half2 hi = __floats2half2_rn(v01, v11);
            quads[z * PL2 + (ty + 1) * PJ + (tx + 1)] =
                make_uint2(*(unsigned*)&lo, *(unsigned*)&hi);
            if (ty == 0) {   // py=0: rows (-1,0)
                __half2 h0 = __floats2half2_rn(0.f, 0.f);
                __half2 h1 = __floats2half2_rn(v00, v10);
                quads[z * PL2 + (tx + 1)] = make_uint2(*(unsigned*)&h0, *(unsigned*)&h1);
            }
            if (tx == 0) {   // pj=0: cols (-1,0)
                __half2 h0 = __floats2half2_rn(0.f, v00);
                __half2 h1 = __floats2half2_rn(0.f, v01);
                quads[z * PL2 + (ty + 1) * PJ] = make_uint2(*(unsigned*)&h0, *(unsigned*)&h1);
            }
            if (tx == 0 && ty == 0) {  // corner
                __half2 h0 = __floats2half2_rn(0.f, 0.f);
                __half2 h1 = __floats2half2_rn(0.f, v00);
                quads[z * PL2] = make_uint2(*(unsigned*)&h0, *(unsigned*)&h1);
            }
        }
    }

    // per-channel coefficients
    if (tid < FF) {
        const float* p = g_params + (size_t)(b * FF + tid) * 5;
        float c = p[0], s = p[1], sc = p[2], txp = p[3], typ = p[4];
        float kk  = sc * ((float)WW / (WW - 1));           // sc*18/17
        float axx = c * kk,  axy = -s * kk;
        float ayx = s * kk,  ayy =  c * kk;
        float cx = (WW * 0.5f) * (txp - sc * c + sc * s) + (WW - 1) * 0.5f;
        float cy = (HH * 0.5f) * (typ - sc * s - sc * c) + (HH - 1) * 0.5f;

        float iz  = (float)tid * ((float)FF / (FF - 1)) - 0.5f;
        float z0f = floorf(iz);
        float wz  = iz - z0f;
        int   z0  = (int)z0f, z1 = z0 + 1;
        int   l0  = (z0 >= 0) ? z0 * PL2 : ZLAY;   // zero layer if below
        int   l1  = (z1 < FF) ? z1 * PL2 : ZLAY;   // zero layer if above
        int   zp  = l0 | (l1 << 16);

        cfA[tid] = make_float4(axx, axy, cx, wz);
        cfB[tid] = make_float4(ayx, ayy, cy, __int_as_float(zp));
    }
    __syncthreads();

    const float fx = (float)tx, fy = (float)ty;
    float* outb = out + (size_t)b * VOL + tid;

    #pragma unroll 4
    for (int f = 0; f < FF; f++) {
        float4 A  = cfA[f];
        float4 Bv = cfB[f];

        float ix = fmaf(A.x,  fx, fmaf(A.y,  fy, A.z));
        float iy = fmaf(Bv.x, fx, fmaf(Bv.y, fy, Bv.z));
        ix = fminf(fmaxf(ix, -1.f), (float)WW);
        iy = fminf(fmaxf(iy, -1.f), (float)HH);

        int   x0 = __float2int_rd(ix);
        int   y0 = __float2int_rd(iy);
        float wx = ix - (float)x0;
        float wy = iy - (float)y0;

        int zp  = __float_as_int(Bv.w);
        int l0  = zp & 0xFFFF;
        int l1  = zp >> 16;
        int bo  = y0 * PJ + x0 + (PJ + 1);   // (y0+1)*20 + (x0+1)

        uint2 t0 = quads[l0 + bo];
        uint2 t1 = quads[l1 + bo];

        float2 r00 = __half22float2(*(__half2*)&t0.x);  // z0, row y0
        float2 r01 = __half22float2(*(__half2*)&t0.y);  // z0, row y0+1
        float2 r10 = __half22float2(*(__half2*)&t1.x);  // z1, row y0
        float2 r11 = __half22float2(*(__half2*)&t1.y);  // z1, row y0+1

        float h00 = fmaf(wx, r00.y - r00.x, r00.x);
        float h01 = fmaf(wx, r01.y - r01.x, r01.x);
        float h10 = fmaf(wx, r10.y - r10.x, r10.x);
        float h11 = fmaf(wx, r11.y - r11.x, r11.x);

        float s0 = fmaf(wy, h01 - h00, h00);
        float s1 = fmaf(wy, h11 - h10, h10);

        outb[f * HW] = fmaf(A.w, s1 - s0, s0);
    }
}

// ---------------------------------------------------------------------------
// Launch
// ---------------------------------------------------------------------------
extern "C" void kernel_launch(void* const* d_in, const int* in_sizes, int n_in,
                              void* d_out, int out_size)
{
    const float* feature_map = (const float*)d_in[0];
    const float* para_code   = (const float*)d_in[1];
    const float* W1          = (const float*)d_in[2];
    const float* b1          = (const float*)d_in[3];
    const float* Ws          = (const float*)d_in[4];
    const float* bs          = (const float*)d_in[5];
    const float* Wr          = (const float*)d_in[6];
    const float* br          = (const float*)d_in[7];
    const float* Wt          = (const float*)d_in[8];
    const float* bt          = (const float*)d_in[9];
    float*       out         = (float*)d_out;

    int B = in_sizes[1] / PP;
    if (B > MAXB) B = MAXB;

    const int samp_smem = PTOT * sizeof(uint2);   // 67200
    cudaFuncSetAttribute(adaat_sample_kernel,
                         cudaFuncAttributeMaxDynamicSharedMemorySize, samp_smem);

    adaat_params_kernel<<<(B + BM - 1) / BM, 256>>>(
        para_code, B, W1, b1, Ws, bs, Wr, br, Wt, bt);
    adaat_sample_kernel<<<B, dim3(WW, HH), samp_smem>>>(feature_map, out);
}

// round 7
// speedup vs baseline: 1.2600x; 1.2600x over previous
#include <cuda_runtime.h>
#include <cuda_bf16.h>
#include <cuda_fp16.h>
#include <math.h>

// Problem constants
#define PP   256
#define FF   20
#define HH   18
#define WW   18
#define HW   (HH*WW)      // 324
#define VOL  (FF*HH*WW)   // 6480
#define MAXB 4096
#define PI_F 3.14159f

// Sampler pair volume: per layer 21 rows x 21 half2, 20 layers
#define PROW 21
#define PLAY (PROW*PROW)  // 441
#define PVOL (FF*PLAY)    // 8820 half2 = 35280 B

// Device scratch
__device__ float g_h[MAXB * PP];            // hidden activations
__device__ float g_params[MAXB * FF * 5];   // c, s, scale, tx, ty per (b,f)

// ---------------------------------------------------------------------------
// f32x2 helpers (FFMA2 via PTX)
// ---------------------------------------------------------------------------
typedef unsigned long long u64;

__device__ __forceinline__ u64 pack2(float lo, float hi) {
    u64 d;
    asm("mov.b64 %0, {%1, %2};" : "=l"(d)
        : "r"(__float_as_uint(lo)), "r"(__float_as_uint(hi)));
    return d;
}
__device__ __forceinline__ u64 pack2dup(float v) {
    u64 d;
    asm("mov.b64 %0, {%1, %1};" : "=l"(d) : "r"(__float_as_uint(v)));
    return d;
}
__device__ __forceinline__ u64 fma2(u64 a, u64 b, u64 c) {
    u64 d;
    asm("fma.rn.f32x2 %0, %1, %2, %3;" : "=l"(d) : "l"(a), "l"(b), "l"(c));
    return d;
}
__device__ __forceinline__ float2 unpack2(u64 v) {
    unsigned lo, hi;
    asm("mov.b64 {%0, %1}, %2;" : "=r"(lo), "=r"(hi) : "l"(v));
    float2 f; f.x = __uint_as_float(lo); f.y = __uint_as_float(hi);
    return f;
}

// ---------------------------------------------------------------------------
// Kernel 1: h = relu(pc @ W1 + b1) — tiled SGEMM (R5, proven 23 us)
// BM=64, BN=64, BK=32, 256 threads, 4x4 thread tile. grid = (B/64, 4)
// ---------------------------------------------------------------------------
#define K1_BM 64
#define K1_BN 64
#define K1_BK 32
#define K1_AS 68

__global__ __launch_bounds__(256) void adaat_hidden_kernel(
    const float* __restrict__ pc, int B,
    const float* __restrict__ W1, const float* __restrict__ b1)
{
    __shared__ float As[K1_BK * K1_AS];
    __shared__ float Bs[K1_BK * K1_AS];

    const int b0  = blockIdx.x * K1_BM;
    const int n0  = blockIdx.y * K1_BN;
    const int tid = threadIdx.x;
    const int tc  = tid & 15;
    const int tr  = tid >> 4;

    u64 acc[4][2];
    {
        float4 bj = *(const float4*)(b1 + n0 + tc * 4);
        u64 lo = pack2(bj.x, bj.y), hi = pack2(bj.z, bj.w);
        #pragma unroll
        for (int i = 0; i < 4; i++) { acc[i][0] = lo; acc[i][1] = hi; }
    }

    for (int kt = 0; kt < PP; kt += K1_BK) {
        #pragma unroll
        for (int p = 0; p < 8; p++) {
            int idx = p * 256 + tid;
            int row = idx >> 5;
            int kk  = idx & 31;
            float v = (b0 + row < B) ? pc[(size_t)(b0 + row) * PP + kt + kk] : 0.f;
            As[kk * K1_AS + row] = v;
        }
        #pragma unroll
        for (int p = 0; p < 8; p++) {
            int idx = p * 256 + tid;
            int kk  = idx >> 6;
            int col = idx & 63;
            Bs[kk * K1_AS + col] = W1[(size_t)(kt + kk) * PP + n0 + col];
        }
        __syncthreads();

        #pragma unroll
        for (int kk = 0; kk < K1_BK; kk++) {
            float4 a = *(const float4*)(As + kk * K1_AS + tr * 4);
            float4 w = *(const float4*)(Bs + kk * K1_AS + tc * 4);
            u64 wlo = pack2(w.x, w.y), whi = pack2(w.z, w.w);
            u64 a0 = pack2dup(a.x), a1 = pack2dup(a.y);
            u64 a2 = pack2dup(a.z), a3 = pack2dup(a.w);
            acc[0][0] = fma2(a0, wlo, acc[0][0]); acc[0][1] = fma2(a0, whi, acc[0][1]);
            acc[1][0] = fma2(a1, wlo, acc[1][0]); acc[1][1] = fma2(a1, whi, acc[1][1]);
            acc[2][0] = fma2(a2, wlo, acc[2][0]); acc[2][1] = fma2(a2, whi, acc[2][1]);
            acc[3][0] = fma2(a3, wlo, acc[3][0]); acc[3][1] = fma2(a3, whi, acc[3][1]);
        }
        __syncthreads();
    }

    #pragma unroll
    for (int i = 0; i < 4; i++) {
        int row = b0 + tr * 4 + i;
        if (row >= B) break;
        float2 v0 = unpack2(acc[i][0]);
        float2 v1 = unpack2(acc[i][1]);
        float4 o;
        o.x = fmaxf(v0.x, 0.f); o.y = fmaxf(v0.y, 0.f);
        o.z = fmaxf(v1.x, 0.f); o.w = fmaxf(v1.y, 0.f);
        *(float4*)(g_h + (size_t)row * PP + n0 + tc * 4) = o;
    }
}

// ---------------------------------------------------------------------------
// Kernel 2: heads — (B x 80) = h @ [Ws|Wr|Wt] + bias, activations -> g_params.
// BM=16 rows/block -> 256 blocks. 160 threads; thread tile = 2 rows x 4 cols.
// h tile + weight slices staged in SMEM.
// ---------------------------------------------------------------------------
#define H2_BM  16
#define H2_HS  18        // hs stride (even -> aligned LDS.64 row-pairs)

__device__ __forceinline__ float4 head_bias(int cg,
    const float* bs, const float* br, const float* bt)
{
    if (cg < 5)  return ((const float4*)bs)[cg];
    if (cg < 10) return ((const float4*)br)[cg - 5];
    return ((const float4*)bt)[cg - 10];
}

__device__ __forceinline__ void head_store(int row, int B, int cg, const float* o4)
{
    if (row >= B) return;
    float* pb = g_params + (size_t)row * (FF * 5);
    if (cg < 5) {
        #pragma unroll
        for (int ci = 0; ci < 4; ci++)
            pb[(cg * 4 + ci) * 5 + 2] = 2.f / (1.f + expf(-o4[ci]));
    } else if (cg < 10) {
        #pragma unroll
        for (int ci = 0; ci < 4; ci++) {
            float ang = tanhf(o4[ci]) * PI_F;
            int f = (cg - 5) * 4 + ci;
            pb[f * 5 + 0] = cosf(ang);
            pb[f * 5 + 1] = sinf(ang);
        }
    } else {
        #pragma unroll
        for (int ci = 0; ci < 4; ci++) {
            int o = (cg - 10) * 4 + ci;
            pb[(o >> 1) * 5 + 3 + (o & 1)] = tanhf(o4[ci]);
        }
    }
}

__global__ __launch_bounds__(160) void adaat_heads_kernel(
    int B,
    const float* __restrict__ Ws, const float* __restrict__ bs,
    const float* __restrict__ Wr, const float* __restrict__ br,
    const float* __restrict__ Wt, const float* __restrict__ bt)
{
    __shared__ float hs[PP * H2_HS];    // [k][row], 18432 B
    __shared__ float Wss[32 * 80];      // weight slice, 10240 B

    const int b0  = blockIdx.x * H2_BM;
    const int tid = threadIdx.x;

    // load h tile (coalesced over k)
    for (int idx = tid; idx < H2_BM * PP; idx += 160) {
        int row = idx >> 8;
        int k   = idx & (PP - 1);
        float v = (b0 + row < B) ? g_h[(size_t)(b0 + row) * PP + k] : 0.f;
        hs[k * H2_HS + row] = v;
    }

    const int rp = tid / 20;      // row pair 0..7
    const int cg = tid - rp * 20; // col group 0..19

    float o0[4], o1[4];
    {
        float4 bb = head_bias(cg, bs, br, bt);
        o0[0] = bb.x; o0[1] = bb.y; o0[2] = bb.z; o0[3] = bb.w;
        o1[0] = bb.x; o1[1] = bb.y; o1[2] = bb.z; o1[3] = bb.w;
    }

    for (int kt = 0; kt < PP; kt += 32) {
        // stage [Ws|Wr|Wt] rows kt..kt+31 -> Wss[kk][0..79]
        #pragma unroll
        for (int p = 0; p < 16; p++) {
            int idx = p * 160 + tid;
            int kk  = idx / 80;
            int c   = idx - kk * 80;
            int k   = kt + kk;
            float v;
            if (c < 20)      v = Ws[(size_t)k * 20 + c];
            else if (c < 40) v = Wr[(size_t)k * 20 + (c - 20)];
            else             v = Wt[(size_t)k * 40 + (c - 40)];
            Wss[kk * 80 + c] = v;
        }
        __syncthreads();

        #pragma unroll 8
        for (int kk = 0; kk < 32; kk++) {
            float2 h2 = *(const float2*)(hs + (kt + kk) * H2_HS + rp * 2);
            float4 w  = *(const float4*)(Wss + kk * 80 + cg * 4);
            o0[0] = fmaf(h2.x, w.x, o0[0]);
            o0[1] = fmaf(h2.x, w.y, o0[1]);
            o0[2] = fmaf(h2.x, w.z, o0[2]);
            o0[3] = fmaf(h2.x, w.w, o0[3]);
            o1[0] = fmaf(h2.y, w.x, o1[0]);
            o1[1] = fmaf(h2.y, w.y, o1[1]);
            o1[2] = fmaf(h2.y, w.z, o1[2]);
            o1[3] = fmaf(h2.y, w.w, o1[3]);
        }
        __syncthreads();
    }

    head_store(b0 + rp * 2,     B, cg, o0);
    head_store(b0 + rp * 2 + 1, B, cg, o1);
}

// ---------------------------------------------------------------------------
// Kernel 3: trilinear sample (R4 proven layout), one CTA per batch element,
// block (18,18). Volume as half2 pairs with zero border; launch_bounds caps
// regs at 32 so 6 CTAs/SM fit.
// ---------------------------------------------------------------------------
__global__ __launch_bounds__(324, 6) void adaat_sample_kernel(
    const float* __restrict__ fm, float* __restrict__ out)
{
    const int b   = blockIdx.x;
    const int tx  = threadIdx.x;      // 0..17
    const int ty  = threadIdx.y;      // 0..17
    const int tid = ty * WW + tx;

    __shared__ __half2 pairs[PVOL];   // 35280 B
    __shared__ float4  cfA[FF];       // axx, axy, cx, zw0
    __shared__ float4  cfB[FF];       // ayx, ayy, cy, zw1
    __shared__ int2    zb[FF];

    {
        float4* p4 = (float4*)pairs;
        for (int i = tid; i < PVOL / 4; i += HW)
            p4[i] = make_float4(0.f, 0.f, 0.f, 0.f);
    }
    __syncthreads();

    {
        const float* src = fm + (size_t)b * VOL + ty * WW + tx;
        __half2* dst = pairs + (ty + 1) * PROW + (tx + 1);
        #pragma unroll
        for (int z = 0; z < FF; z++) {
            float val   = src[z * HW];
            float right = (tx < WW - 1) ? src[z * HW + 1] : 0.f;
            dst[z * PLAY] = __floats2half2_rn(val, right);
            if (tx == 0)
                pairs[z * PLAY + (ty + 1) * PROW] = __floats2half2_rn(0.f, val);
        }
    }

    if (tid < FF) {
        const float* p = g_params + (size_t)(b * FF + tid) * 5;
        float c = p[0], s = p[1], sc = p[2], txp = p[3], typ = p[4];
        float kk  = sc * ((float)WW / (WW - 1));
        float axx = c * kk,  axy = -s * kk;
        float ayx = s * kk,  ayy =  c * kk;
        float cx = (WW * 0.5f) * (txp - sc * c + sc * s) + (WW - 1) * 0.5f;
        float cy = (HH * 0.5f) * (typ - sc * s - sc * c) + (HH - 1) * 0.5f;

        float iz  = (float)tid * ((float)FF / (FF - 1)) - 0.5f;
        float z0f = floorf(iz);
        float wz  = iz - z0f;
        int   z0  = (int)z0f, z1 = z0 + 1;
        float w0  = (z0 >= 0 && z0 < FF) ? (1.f - wz) : 0.f;
        float w1  = (z1 >= 0 && z1 < FF) ? wz         : 0.f;
        int   zb0 = min(max(z0, 0), FF - 1) * PLAY;
        int   zb1 = min(max(z1, 0), FF - 1) * PLAY;

        cfA[tid] = make_float4(axx, axy, cx, w0);
        cfB[tid] = make_float4(ayx, ayy, cy, w1);
        zb[tid]  = make_int2(zb0, zb1);
    }
    __syncthreads();

    const float fx = (float)tx, fy = (float)ty;
    float* outb = out + (size_t)b * VOL + tid;

    #pragma unroll 4
    for (int f = 0; f < FF; f++) {
        float4 A  = cfA[f];
        float4 Bv = cfB[f];
        int2   zo = zb[f];

        float ix = fmaf(A.x,  fx, fmaf(A.y,  fy, A.z));
        float iy = fmaf(Bv.x, fx, fmaf(Bv.y, fy, Bv.z));
        ix = fminf(fmaxf(ix, -1.f), (float)WW);
        iy = fminf(fmaxf(iy, -1.f), (float)HH);

        int   x0 = __float2int_rd(ix);
        int   y0 = __float2int_rd(iy);
        float wx = ix - (float)x0;
        float wy = iy - (float)y0;

        int bo = y0 * PROW + x0 + (PROW + 1);

        float2 f00 = __half22float2(pairs[zo.x + bo]);
        float2 f01 = __half22float2(pairs[zo.x + bo + PROW]);
        float2 f10 = __half22float2(pairs[zo.y + bo]);
        float2 f11 = __half22float2(pairs[zo.y + bo + PROW]);

        float h00 = fmaf(wx, f00.y - f00.x, f00.x);
        float h01 = fmaf(wx, f01.y - f01.x, f01.x);
        float h10 = fmaf(wx, f10.y - f10.x, f10.x);
        float h11 = fmaf(wx, f11.y - f11.x, f11.x);

        float s0 = fmaf(wy, h01 - h00, h00);
        float s1 = fmaf(wy, h11 - h10, h10);

        outb[f * HW] = fmaf(A.w, s0, Bv.w * s1);
    }
}

// ---------------------------------------------------------------------------
// Launch
// ---------------------------------------------------------------------------
extern "C" void kernel_launch(void* const* d_in, const int* in_sizes, int n_in,
                              void* d_out, int out_size)
{
    const float* feature_map = (const float*)d_in[0];
    const float* para_code   = (const float*)d_in[1];
    const float* W1          = (const float*)d_in[2];
    const float* b1          = (const float*)d_in[3];
    const float* Ws          = (const float*)d_in[4];
    const float* bs          = (const float*)d_in[5];
    const float* Wr          = (const float*)d_in[6];
    const float* br          = (const float*)d_in[7];
    const float* Wt          = (const float*)d_in[8];
    const float* bt          = (const float*)d_in[9];
    float*       out         = (float*)d_out;

    int B = in_sizes[1] / PP;
    if (B > MAXB) B = MAXB;

    dim3 g1((B + K1_BM - 1) / K1_BM, PP / K1_BN);
    adaat_hidden_kernel<<<g1, 256>>>(para_code, B, W1, b1);
    adaat_heads_kernel<<<(B + H2_BM - 1) / H2_BM, 160>>>(B, Ws, bs, Wr, br, Wt, bt);
    adaat_sample_kernel<<<B, dim3(WW, HH)>>>(feature_map, out);
}

// round 9
// speedup vs baseline: 1.2627x; 1.0021x over previous
#include <cuda_runtime.h>
#include <cuda_bf16.h>
#include <cuda_fp16.h>
#include <math.h>

// Problem constants
#define PP   256
#define FF   20
#define HH   18
#define WW   18
#define HW   (HH*WW)      // 324
#define VOL  (FF*HH*WW)   // 6480
#define MAXB 4096
#define PI_F 3.14159f

// Sampler pair volume: 21x21 half2 per layer, FF layers + 1 zero layer
#define PROW 21
#define PLAY (PROW*PROW)      // 441
#define ZOFF (FF*PLAY)        // 8820 = zero layer offset
#define PVOLZ 9264            // 21 layers (9261) padded to /4

// Device scratch
__device__ float g_h[MAXB * PP];
__device__ float g_params[MAXB * FF * 5];   // c, s, scale, tx, ty

// ---------------------------------------------------------------------------
// f32x2 helpers
// ---------------------------------------------------------------------------
typedef unsigned long long u64;

__device__ __forceinline__ u64 pack2(float lo, float hi) {
    u64 d;
    asm("mov.b64 %0, {%1, %2};" : "=l"(d)
        : "r"(__float_as_uint(lo)), "r"(__float_as_uint(hi)));
    return d;
}
__device__ __forceinline__ u64 pack2dup(float v) {
    u64 d;
    asm("mov.b64 %0, {%1, %1};" : "=l"(d) : "r"(__float_as_uint(v)));
    return d;
}
__device__ __forceinline__ u64 fma2(u64 a, u64 b, u64 c) {
    u64 d;
    asm("fma.rn.f32x2 %0, %1, %2, %3;" : "=l"(d) : "l"(a), "l"(b), "l"(c));
    return d;
}
__device__ __forceinline__ float2 unpack2(u64 v) {
    unsigned lo, hi;
    asm("mov.b64 {%0, %1}, %2;" : "=r"(lo), "=r"(hi) : "l"(v));
    float2 f; f.x = __uint_as_float(lo); f.y = __uint_as_float(hi);
    return f;
}

// ---------------------------------------------------------------------------
// Kernel 1: h = relu(pc @ W1 + b1).  BM=64, BN=32, BK=32, 128 threads,
// 4x4 thread tile with FFMA2.  grid = (B/64, 8) = 512 blocks.
// ---------------------------------------------------------------------------
#define K1_BM 64
#define K1_BN 32
#define K1_BK 32
#define K1_AS 68
#define K1_BS 36

__global__ __launch_bounds__(128) void adaat_hidden_kernel(
    const float* __restrict__ pc, int B,
    const float* __restrict__ W1, const float* __restrict__ b1)
{
    __shared__ float As[K1_BK * K1_AS];   // [kk][row]
    __shared__ float Bs[K1_BK * K1_BS];   // [kk][col]

    const int b0  = blockIdx.x * K1_BM;
    const int n0  = blockIdx.y * K1_BN;
    const int tid = threadIdx.x;
    const int tc  = tid & 7;        // col group 0..7
    const int tr  = tid >> 3;       // row group 0..15

    u64 acc[4][2];
    {
        float4 bj = *(const float4*)(b1 + n0 + tc * 4);
        u64 lo = pack2(bj.x, bj.y), hi = pack2(bj.z, bj.w);
        #pragma unroll
        for (int i = 0; i < 4; i++) { acc[i][0] = lo; acc[i][1] = hi; }
    }

    for (int kt = 0; kt < PP; kt += K1_BK) {
        // A tile: pc[b0+row][kt+kk] -> As[kk][row]  (2048 elems, 16/thread)
        #pragma unroll
        for (int p = 0; p < 16; p++) {
            int idx = p * 128 + tid;
            int row = idx >> 5;
            int kk  = idx & 31;
            float v = (b0 + row < B) ? pc[(size_t)(b0 + row) * PP + kt + kk] : 0.f;
            As[kk * K1_AS + row] = v;
        }
        // B tile: W1[kt+kk][n0+col] -> Bs[kk][col]  (1024 elems, 8/thread)
        #pragma unroll
        for (int p = 0; p < 8; p++) {
            int idx = p * 128 + tid;
            int kk  = idx >> 5;
            int col = idx & 31;
            Bs[kk * K1_BS + col] = W1[(size_t)(kt + kk) * PP + n0 + col];
        }
        __syncthreads();

        #pragma unroll
        for (int kk = 0; kk < K1_BK; kk++) {
            float4 a = *(const float4*)(As + kk * K1_AS + tr * 4);
            float4 w = *(const float4*)(Bs + kk * K1_BS + tc * 4);
            u64 wlo = pack2(w.x, w.y), whi = pack2(w.z, w.w);
            u64 a0 = pack2dup(a.x), a1 = pack2dup(a.y);
            u64 a2 = pack2dup(a.z), a3 = pack2dup(a.w);
            acc[0][0] = fma2(a0, wlo, acc[0][0]); acc[0][1] = fma2(a0, whi, acc[0][1]);
            acc[1][0] = fma2(a1, wlo, acc[1][0]); acc[1][1] = fma2(a1, whi, acc[1][1]);
            acc[2][0] = fma2(a2, wlo, acc[2][0]); acc[2][1] = fma2(a2, whi, acc[2][1]);
            acc[3][0] = fma2(a3, wlo, acc[3][0]); acc[3][1] = fma2(a3, whi, acc[3][1]);
        }
        __syncthreads();
    }

    #pragma unroll
    for (int i = 0; i < 4; i++) {
        int row = b0 + tr * 4 + i;
        if (row >= B) break;
        float2 v0 = unpack2(acc[i][0]);
        float2 v1 = unpack2(acc[i][1]);
        float4 o;
        o.x = fmaxf(v0.x, 0.f); o.y = fmaxf(v0.y, 0.f);
        o.z = fmaxf(v1.x, 0.f); o.w = fmaxf(v1.y, 0.f);
        *(float4*)(g_h + (size_t)row * PP + n0 + tc * 4) = o;
    }
}

// ---------------------------------------------------------------------------
// Kernel 2: heads — (B x 80) = h @ [Ws|Wr|Wt] + bias, activations -> g_params.
// BM=16 rows/block -> 256 blocks, 160 threads, 2-row x 4-col tile.
// ---------------------------------------------------------------------------
#define H2_BM  16
#define H2_HS  18

__device__ __forceinline__ float4 head_bias(int cg,
    const float* bs, const float* br, const float* bt)
{
    if (cg < 5)  return ((const float4*)bs)[cg];
    if (cg < 10) return ((const float4*)br)[cg - 5];
    return ((const float4*)bt)[cg - 10];
}

__device__ __forceinline__ void head_store(int row, int B, int cg, const float* o4)
{
    if (row >= B) return;
    float* pb = g_params + (size_t)row * (FF * 5);
    if (cg < 5) {
        #pragma unroll
        for (int ci = 0; ci < 4; ci++)
            pb[(cg * 4 + ci) * 5 + 2] = 2.f / (1.f + expf(-o4[ci]));
    } else if (cg < 10) {
        #pragma unroll
        for (int ci = 0; ci < 4; ci++) {
            float ang = tanhf(o4[ci]) * PI_F;
            int f = (cg - 5) * 4 + ci;
            pb[f * 5 + 0] = cosf(ang);
            pb[f * 5 + 1] = sinf(ang);
        }
    } else {
        #pragma unroll
        for (int ci = 0; ci < 4; ci++) {
            int o = (cg - 10) * 4 + ci;
            pb[(o >> 1) * 5 + 3 + (o & 1)] = tanhf(o4[ci]);
        }
    }
}

__global__ __launch_bounds__(160) void adaat_heads_kernel(
    int B,
    const float* __restrict__ Ws, const float* __restrict__ bs,
    const float* __restrict__ Wr, const float* __restrict__ br,
    const float* __restrict__ Wt, const float* __restrict__ bt)
{
    __shared__ float hs[PP * H2_HS];
    __shared__ float Wss[32 * 80];

    const int b0  = blockIdx.x * H2_BM;
    const int tid = threadIdx.x;

    for (int idx = tid; idx < H2_BM * PP; idx += 160) {
        int row = idx >> 8;
        int k   = idx & (PP - 1);
        float v = (b0 + row < B) ? g_h[(size_t)(b0 + row) * PP + k] : 0.f;
        hs[k * H2_HS + row] = v;
    }

    const int rp = tid / 20;
    const int cg = tid - rp * 20;

    float o0[4], o1[4];
    {
        float4 bb = head_bias(cg, bs, br, bt);
        o0[0] = bb.x; o0[1] = bb.y; o0[2] = bb.z; o0[3] = bb.w;
        o1[0] = bb.x; o1[1] = bb.y; o1[2] = bb.z; o1[3] = bb.w;
    }

    for (int kt = 0; kt < PP; kt += 32) {
        #pragma unroll
        for (int p = 0; p < 16; p++) {
            int idx = p * 160 + tid;
            int kk  = idx / 80;
            int c   = idx - kk * 80;
            int k   = kt + kk;
            float v;
            if (c < 20)      v = Ws[(size_t)k * 20 + c];
            else if (c < 40) v = Wr[(size_t)k * 20 + (c - 20)];
            else             v = Wt[(size_t)k * 40 + (c - 40)];
            Wss[kk * 80 + c] = v;
        }
        __syncthreads();

        #pragma unroll 8
        for (int kk = 0; kk < 32; kk++) {
            float2 h2 = *(const float2*)(hs + (kt + kk) * H2_HS + rp * 2);
            float4 w  = *(const float4*)(Wss + kk * 80 + cg * 4);
            o0[0] = fmaf(h2.x, w.x, o0[0]);
            o0[1] = fmaf(h2.x, w.y, o0[1]);
            o0[2] = fmaf(h2.x, w.z, o0[2]);
            o0[3] = fmaf(h2.x, w.w, o0[3]);
            o1[0] = fmaf(h2.y, w.x, o1[0]);
            o1[1] = fmaf(h2.y, w.y, o1[1]);
            o1[2] = fmaf(h2.y, w.z, o1[2]);
            o1[3] = fmaf(h2.y, w.w, o1[3]);
        }
        __syncthreads();
    }

    head_store(b0 + rp * 2,     B, cg, o0);
    head_store(b0 + rp * 2 + 1, B, cg, o1);
}

// ---------------------------------------------------------------------------
// Kernel 3: trilinear sample. One CTA per batch, block (18,18).
// half2 pair volume with zero border + dedicated zero layer for z-edges.
// Per channel: 2 packed layer offsets + wz -> out = s0 + wz*(s1-s0).
// launch_bounds(324,5): reg cap 37 >= natural usage, 5 CTAs/SM.
// ---------------------------------------------------------------------------
__global__ __launch_bounds__(324, 5) void adaat_sample_kernel(
    const float* __restrict__ fm, float* __restrict__ out)
{
    const int b   = blockIdx.x;
    const int tx  = threadIdx.x;      // 0..17
    const int ty  = threadIdx.y;      // 0..17
    const int tid = ty * WW + tx;

    __shared__ __half2 pairs[PVOLZ];  // 37056 B (incl. zero layer)
    __shared__ float4  cfA[FF];       // axx, axy, cx, wz
    __shared__ float4  cfB[FF];       // ayx, ayy, cy, bits(l0 | l1<<16)

    // zero everything (incl. zero layer)
    {
        float4* p4 = (float4*)pairs;
        for (int i = tid; i < PVOLZ / 4; i += HW)
            p4[i] = make_float4(0.f, 0.f, 0.f, 0.f);
    }
    __syncthreads();

    // fill interior: pairs[z][ty+1][tx+1] = (V(tx), V(tx+1)); col 0 = (0, V(0))
    {
        const float* src = fm + (size_t)b * VOL + ty * WW + tx;
        __half2* dst = pairs + (ty + 1) * PROW + (tx + 1);
        #pragma unroll
        for (int z = 0; z < FF; z++) {
            float val   = src[z * HW];
            float right = (tx < WW - 1) ? src[z * HW + 1] : 0.f;
            dst[z * PLAY] = __floats2half2_rn(val, right);
            if (tx == 0)
                pairs[z * PLAY + (ty + 1) * PROW] = __floats2half2_rn(0.f, val);
        }
    }

    if (tid < FF) {
        const float* p = g_params + (size_t)(b * FF + tid) * 5;
        float c = p[0], s = p[1], sc = p[2], txp = p[3], typ = p[4];
        float kk  = sc * ((float)WW / (WW - 1));
        float axx = c * kk,  axy = -s * kk;
        float ayx = s * kk,  ayy =  c * kk;
        float cx = (WW * 0.5f) * (txp - sc * c + sc * s) + (WW - 1) * 0.5f;
        float cy = (HH * 0.5f) * (typ - sc * s - sc * c) + (HH - 1) * 0.5f;

        float iz  = (float)tid * ((float)FF / (FF - 1)) - 0.5f;
        float z0f = floorf(iz);
        float wz  = iz - z0f;
        int   z0  = (int)z0f, z1 = z0 + 1;
        int   l0  = (z0 >= 0) ? z0 * PLAY : ZOFF;   // zero layer below
        int   l1  = (z1 < FF) ? z1 * PLAY : ZOFF;   // zero layer above
        int   zp  = l0 | (l1 << 16);

        cfA[tid] = make_float4(axx, axy, cx, wz);
        cfB[tid] = make_float4(ayx, ayy, cy, __int_as_float(zp));
    }
    __syncthreads();

    const float fx = (float)tx, fy = (float)ty;
    float* outb = out + (size_t)b * VOL + tid;

    #pragma unroll 4
    for (int f = 0; f < FF; f++) {
        float4 A  = cfA[f];
        float4 Bv = cfB[f];

        float ix = fmaf(A.x,  fx, fmaf(A.y,  fy, A.z));
        float iy = fmaf(Bv.x, fx, fmaf(Bv.y, fy, Bv.z));
        ix = fminf(fmaxf(ix, -1.f), (float)WW);
        iy = fminf(fmaxf(iy, -1.f), (float)HH);

        int   x0 = __float2int_rd(ix);
        int   y0 = __float2int_rd(iy);
        float wx = ix - (float)x0;
        float wy = iy - (float)y0;

        int zp = __float_as_int(Bv.w);
        int l0 = zp & 0xFFFF;
        int l1 = zp >> 16;
        int bo = y0 * PROW + x0 + (PROW + 1);

        float2 f00 = __half22float2(pairs[l0 + bo]);
        float2 f01 = __half22float2(pairs[l0 + bo + PROW]);
        float2 f10 = __half22float2(pairs[l1 + bo]);
        float2 f11 = __half22float2(pairs[l1 + bo + PROW]);

        float h00 = fmaf(wx, f00.y - f00.x, f00.x);
        float h01 = fmaf(wx, f01.y - f01.x, f01.x);
        float h10 = fmaf(wx, f10.y - f10.x, f10.x);
        float h11 = fmaf(wx, f11.y - f11.x, f11.x);

        float s0 = fmaf(wy, h01 - h00, h00);
        float s1 = fmaf(wy, h11 - h10, h10);

        outb[f * HW] = fmaf(A.w, s1 - s0, s0);
    }
}

// ---------------------------------------------------------------------------
// Launch
// ---------------------------------------------------------------------------
extern "C" void kernel_launch(void* const* d_in, const int* in_sizes, int n_in,
                              void* d_out, int out_size)
{
    const float* feature_map = (const float*)d_in[0];
    const float* para_code   = (const float*)d_in[1];
    const float* W1          = (const float*)d_in[2];
    const float* b1          = (const float*)d_in[3];
    const float* Ws          = (const float*)d_in[4];
    const float* bs          = (const float*)d_in[5];
    const float* Wr          = (const float*)d_in[6];
    const float* br          = (const float*)d_in[7];
    const float* Wt          = (const float*)d_in[8];
    const float* bt          = (const float*)d_in[9];
    float*       out         = (float*)d_out;

    int B = in_sizes[1] / PP;
    if (B > MAXB) B = MAXB;

    dim3 g1((B + K1_BM - 1) / K1_BM, PP / K1_BN);
    adaat_hidden_kernel<<<g1, 128>>>(para_code, B, W1, b1);
    adaat_heads_kernel<<<(B + H2_BM - 1) / H2_BM, 160>>>(B, Ws, bs, Wr, br, Wt, bt);
    adaat_sample_kernel<<<B, dim3(WW, HH)>>>(feature_map, out);
}